// round 17
// baseline (speedup 1.0000x reference)
#include <cuda_runtime.h>
#include <cuda_fp16.h>
#include <cstdint>
#include <math.h>

// ---------------- problem constants ----------------
#define NTOT 4
#define CHN  256
#define HSZ  128
#define WSZ  128
#define HWSZ 16384
#define MTOT 65536
#define KTAP 9
#define EPSV 1e-5f
#define OMSP 128

typedef __half fp16;

// ---------------- scratch ----------------
__device__ fp16  g_xh[MTOT*CHN];                     // x transposed, fp16
__device__ fp16  g_yh[MTOT*CHN];                     // y fp16
__device__ fp16  g_sh[MTOT*CHN];                     // sampled fp16
__device__ fp16  g_v [MTOT*CHN];                     // value proj fp16
__device__ float g_om[MTOT*OMSP];                    // offsets+masks
__device__ fp16  g_whi[896*CHN];                     // weights fp16

// ---------------- helpers ----------------
__device__ __forceinline__ uint32_t smem_u32(const void* p){
    uint32_t a;
    asm("{ .reg .u64 t; cvta.to.shared.u64 t, %1; cvt.u32.u64 %0, t; }" : "=r"(a) : "l"(p));
    return a;
}
__device__ __forceinline__ void cpasync16(uint32_t dst, const void* src){
    asm volatile("cp.async.cg.shared.global [%0], [%1], 16;"
                 :: "r"(dst), "l"(src) : "memory");
}
#define CP_COMMIT()  asm volatile("cp.async.commit_group;" ::: "memory")
#define CP_WAIT(n)   asm volatile("cp.async.wait_group %0;" :: "n"(n) : "memory")

__device__ __forceinline__ void ldsm4(uint32_t& a0, uint32_t& a1, uint32_t& a2,
                                      uint32_t& a3, uint32_t addr){
    asm volatile("ldmatrix.sync.aligned.m8n8.x4.shared.b16 {%0,%1,%2,%3}, [%4];"
                 : "=r"(a0), "=r"(a1), "=r"(a2), "=r"(a3) : "r"(addr));
}
__device__ __forceinline__ void ldsm2(uint32_t& b0, uint32_t& b1, uint32_t addr){
    asm volatile("ldmatrix.sync.aligned.m8n8.x2.shared.b16 {%0,%1}, [%2];"
                 : "=r"(b0), "=r"(b1) : "r"(addr));
}
__device__ __forceinline__ void mma16816(float* c, const uint32_t* a,
                                         const uint32_t* b){
    asm volatile(
        "mma.sync.aligned.m16n8k16.row.col.f32.f16.f16.f32 "
        "{%0,%1,%2,%3}, {%4,%5,%6,%7}, {%8,%9}, {%0,%1,%2,%3};"
        : "+f"(c[0]), "+f"(c[1]), "+f"(c[2]), "+f"(c[3])
        : "r"(a[0]), "r"(a[1]), "r"(a[2]), "r"(a[3]), "r"(b[0]), "r"(b[1]));
}
__device__ __forceinline__ uint32_t pack2h(fp16 a, fp16 b){
    __half2 h; h.x = a; h.y = b;
    return *reinterpret_cast<uint32_t*>(&h);
}
// 128-byte-row swizzle: row r (0..127), 16B chunk c (0..7)
__device__ __forceinline__ uint32_t swzB(int r, int c){
    return (uint32_t)(r * 128 + ((c ^ (r & 7)) * 16));
}
__device__ __forceinline__ float silu_f(float x){
    return x / (1.f + __expf(-x));
}
// ---- packed f32x2 (Blackwell) ----
__device__ __forceinline__ uint64_t packf2(float x, float y){
    uint64_t r; asm("mov.b64 %0, {%1,%2};" : "=l"(r) : "f"(x), "f"(y)); return r;
}
__device__ __forceinline__ void unpackf2(uint64_t r, float& x, float& y){
    asm("mov.b64 {%0,%1}, %2;" : "=f"(x), "=f"(y) : "l"(r));
}
__device__ __forceinline__ void ffma2(uint64_t& acc, uint64_t a, uint64_t b){
    asm("fma.rn.f32x2 %0, %1, %2, %0;" : "+l"(acc) : "l"(a), "l"(b));
}
// half2 -> packed f32x2 (two cvts + pack; pack is register-pairing only)
__device__ __forceinline__ uint64_t h2_to_f2(uint32_t h2){
    float2 f = __half22float2(*reinterpret_cast<__half2*>(&h2));
    return packf2(f.x, f.y);
}

// ---------------------------------------------------------------------------
// Merged prepass: blocks [0,4096) transpose x NCHW fp32 -> NHWC fp16;
// blocks [4096,4992) pad/convert weights to fp16.
// ---------------------------------------------------------------------------
__global__ __launch_bounds__(256)
void prep(const float* __restrict__ x, fp16* __restrict__ xh,
          const float* __restrict__ conv_w, const float* __restrict__ value_w,
          const float* __restrict__ offset_w, const float* __restrict__ out_w,
          fp16* __restrict__ whi)
{
    const int tid = threadIdx.x;
    if (blockIdx.x >= 4096) {
        int idx = (blockIdx.x - 4096) * 256 + tid;
        int r = idx >> 8, c = idx & 255;
        float v = 0.f;
        if      (r < 256) v = conv_w[r * 256 + c];
        else if (r < 512) v = value_w[(r - 256) * 256 + c];
        else if (r < 640) { int rr = r - 512; if (rr < 112) v = offset_w[rr * 256 + c]; }
        else              v = out_w[(r - 640) * 256 + c];
        whi[idx] = __float2half_rn(v);
        return;
    }
    __shared__ float t[32][129];
    const int bid = blockIdx.x;
    const int n = bid >> 10, c0 = ((bid >> 7) & 7) * 32, hw0 = (bid & 127) * 128;
    const float* src = x + ((size_t)n * 256 + c0) * HWSZ + hw0;
    #pragma unroll
    for (int i = 0; i < 16; i++) {
        int e = tid + i * 256;
        int c = e >> 7, p = e & 127;
        t[c][p] = src[(size_t)c * HWSZ + p];
    }
    __syncthreads();
    int p = tid >> 1, half = tid & 1;
    size_t base = ((size_t)n * HWSZ + hw0 + p) * 256 + c0 + half * 16;
    fp16 hi[16];
    #pragma unroll
    for (int j = 0; j < 16; j++)
        hi[j] = __float2half_rn(t[half * 16 + j][p]);
    *reinterpret_cast<uint4*>(&xh[base])     = *reinterpret_cast<uint4*>(&hi[0]);
    *reinterpret_cast<uint4*>(&xh[base + 8]) = *reinterpret_cast<uint4*>(&hi[8]);
}

// ---------------------------------------------------------------------------
// fp16 HMMA GEMM, BK=64 stages (4 stages, 3 x 32KB smem buffers).
// Grid: x = n-block (fast -> L2 A reuse), y = pixel tile.
// ---------------------------------------------------------------------------
template<int EPI>
__global__ __launch_bounds__(256, 2)
void gemm_fp16(const fp16* __restrict__ Ah, const fp16* __restrict__ Bhi,
               const float* __restrict__ bias, const float* __restrict__ bias2,
               const float* __restrict__ gamma, const float* __restrict__ beta,
               const float* __restrict__ mean,  const float* __restrict__ var,
               float* __restrict__ Co, float* __restrict__ Co2,
               fp16* __restrict__ CoH)
{
    extern __shared__ __align__(16) char dsm[];
    __shared__ float sSC[128], sSH[128];

    const int tid  = threadIdx.x;
    const int wid  = tid >> 5;
    const int lane = tid & 31;
    const int p0   = blockIdx.y * 128;
    const int n0   = blockIdx.x * 128;

    const uint32_t sb = smem_u32(dsm);
    const int STG = 32768;
    auto AH = [&](int s){ return sb + s * STG; };
    auto BH = [&](int s){ return sb + s * STG + 16384; };

    if (tid < 128) {
        int o = n0 + tid;
        float sc = 1.f, sh = 0.f;
        if (EPI == 1) {
            float s_ = gamma[o] * rsqrtf(var[o] + EPSV);
            sc = s_; sh = beta[o] - mean[o] * s_;
        } else if (EPI == 2) {
            float s_ = gamma[o] * rsqrtf(var[o] + EPSV);
            sc = s_; sh = (beta[o] - mean[o] * s_) + bias[o] * s_;
        } else { // EPI 3
            if (o < 256)            sh = bias[o];
            else if (o - 256 < 112) sh = bias2[o - 256];
        }
        sSC[tid] = sc; sSH[tid] = sh;
    }

    auto load_stage = [&](int kt, int s) {
        #pragma unroll
        for (int i = 0; i < 4; i++) {
            int e = tid + i * 256;
            int r = e >> 3, c = e & 7;
            uint32_t d = swzB(r, c);
            cpasync16(AH(s) + d, Ah  + (size_t)(p0 + r) * 256 + kt + c * 8);
            cpasync16(BH(s) + d, Bhi + (size_t)(n0 + r) * 256 + kt + c * 8);
        }
        CP_COMMIT();
    };

    const int wm = (wid >> 2) * 64;
    const int wn = (wid & 3) * 32;

    float acc[4][4][4];
    #pragma unroll
    for (int i = 0; i < 4; i++)
        #pragma unroll
        for (int j = 0; j < 4; j++)
            #pragma unroll
            for (int q = 0; q < 4; q++) acc[i][j][q] = 0.f;

    load_stage(0, 0);
    load_stage(64, 1);

    #pragma unroll 1
    for (int st = 0; st < 4; st++) {
        const int s = st % 3;
        if (st == 3) { CP_WAIT(0); } else { CP_WAIT(1); }
        __syncthreads();
        if (st < 2) load_stage((st + 2) * 64, (st + 2) % 3);

        #pragma unroll
        for (int kk = 0; kk < 4; kk++) {
            const int c0 = kk * 2;
            uint32_t ah[4][4], bh[4][2];
            #pragma unroll
            for (int mt = 0; mt < 4; mt++) {
                int rr = wm + mt * 16 + (lane & 15);
                int cc = c0 + (lane >> 4);
                ldsm4(ah[mt][0], ah[mt][1], ah[mt][2], ah[mt][3],
                      AH(s) + swzB(rr, cc));
            }
            #pragma unroll
            for (int nt = 0; nt < 4; nt++) {
                int rr = wn + nt * 8 + (lane & 7);
                int cc = c0 + ((lane >> 3) & 1);
                ldsm2(bh[nt][0], bh[nt][1], BH(s) + swzB(rr, cc));
            }
            #pragma unroll
            for (int mt = 0; mt < 4; mt++)
                #pragma unroll
                for (int nt = 0; nt < 4; nt++)
                    mma16816(acc[mt][nt], ah[mt], bh[nt]);
        }
    }

    // ---------------- epilogue ----------------
    const int qr = lane >> 2;
    const int qc = (lane & 3) * 2;
    #pragma unroll
    for (int mt = 0; mt < 4; mt++) {
        #pragma unroll
        for (int nt = 0; nt < 4; nt++) {
            int ocl = wn + nt * 8 + qc;
            int o   = n0 + ocl;
            float sc0 = sSC[ocl],     sh0 = sSH[ocl];
            float sc1 = sSC[ocl + 1], sh1 = sSH[ocl + 1];
            #pragma unroll
            for (int half = 0; half < 2; half++) {
                int p  = p0 + wm + mt * 16 + qr + half * 8;
                float v0 = acc[mt][nt][half * 2 + 0] * sc0 + sh0;
                float v1 = acc[mt][nt][half * 2 + 1] * sc1 + sh1;
                if (EPI == 1 || EPI == 2) {
                    v0 = silu_f(v0);
                    v1 = silu_f(v1);
                }
                if (EPI == 1) {
                    *reinterpret_cast<uint32_t*>(&CoH[(size_t)p * 256 + o]) =
                        pack2h(__float2half_rn(v0), __float2half_rn(v1));
                } else if (EPI == 2) {
                    int n = p >> 14, hw = p & 16383;
                    Co[(((size_t)n * 256 + o)     << 14) + hw] = v0;
                    Co[(((size_t)n * 256 + o + 1) << 14) + hw] = v1;
                } else { // EPI 3
                    if (o < 256) {
                        *reinterpret_cast<uint32_t*>(&CoH[(size_t)p * 256 + o]) =
                            pack2h(__float2half_rn(v0), __float2half_rn(v1));
                    } else {
                        *reinterpret_cast<float2*>(&Co2[(size_t)p * OMSP + (o - 256)]) =
                            make_float2(v0, v1);
                    }
                }
            }
        }
    }
}

// ---------------------------------------------------------------------------
// DCNv4 sampling v6: v5 (shuffle tap-dedup) + packed fma.rn.f32x2 accumulate.
// Accumulators are 4 packed float2; per corner 4 FFMA2 instead of 8 FFMA.
// Per-element fma.rn semantics -> bit-identical output vs v4/v5.
// ---------------------------------------------------------------------------
__device__ __forceinline__ void tap_params(
    int k, const float* __restrict__ op, int h, int w,
    float W[4], int R[4])
{
    float ow = op[2 * k];
    float oh = op[2 * k + 1];
    float mk = op[18 + k];
    float lh = (float)(h + k / 3 - 1) + oh;
    float lw = (float)(w + k % 3 - 1) + ow;
    float fh = floorf(lh), fw = floorf(lw);
    int h0 = (int)fh, w0 = (int)fw;
    float dh = lh - fh, dw = lw - fw;
    float w00 = (1.f - dh) * (1.f - dw) * mk;
    float w01 = (1.f - dh) * dw * mk;
    float w10 = dh * (1.f - dw) * mk;
    float w11 = dh * dw * mk;
    bool hv0 = (unsigned)h0 < HSZ;
    bool hv1 = (unsigned)(h0 + 1) < HSZ;
    bool wv0 = (unsigned)w0 < WSZ;
    bool wv1 = (unsigned)(w0 + 1) < WSZ;
    W[0] = (hv0 && wv0) ? w00 : 0.f;
    W[1] = (hv0 && wv1) ? w01 : 0.f;
    W[2] = (hv1 && wv0) ? w10 : 0.f;
    W[3] = (hv1 && wv1) ? w11 : 0.f;
    int h0c = min(max(h0, 0), HSZ - 1);
    int h1c = min(max(h0 + 1, 0), HSZ - 1);
    int w0c = min(max(w0, 0), WSZ - 1);
    int w1c = min(max(w0 + 1, 0), WSZ - 1);
    R[0] = (h0c * WSZ + w0c) << 8;
    R[1] = (h0c * WSZ + w1c) << 8;
    R[2] = (h1c * WSZ + w0c) << 8;
    R[3] = (h1c * WSZ + w1c) << 8;
}

__global__ __launch_bounds__(256)
void dcn_sample(const fp16* __restrict__ v, const float* __restrict__ om,
                fp16* __restrict__ sh)
{
    const int p    = (blockIdx.x * 256 + threadIdx.x) >> 5;   // pixel
    const int lane = threadIdx.x & 31;
    const int g    = lane >> 3;
    const int j    = lane & 7;       // my tap (0..7)
    const int c8   = j * 8;          // channel base within group
    const int n  = p >> 14;
    const int hw = p & (HWSZ - 1);
    const int h = hw >> 7, w = hw & 127;

    const float* op = om + (size_t)p * OMSP + g * 27;
    const int cb = g * 64 + c8;
    const fp16* vb = v + ((size_t)n << 22) + cb;

    float Wm[4]; int Rm[4];
    float W8[4]; int R8[4];
    tap_params(j, op, h, w, Wm, Rm);
    tap_params(8, op, h, w, W8, R8);

    uint64_t acc[4];
    #pragma unroll
    for (int u = 0; u < 4; u++) acc[u] = packf2(0.f, 0.f);

    #define ACC8(R0, R1, R2, R3, V0, V1, V2, V3) do { \
        uint4 q0 = *reinterpret_cast<const uint4*>(vb + (R0)); \
        uint4 q1 = *reinterpret_cast<const uint4*>(vb + (R1)); \
        uint4 q2 = *reinterpret_cast<const uint4*>(vb + (R2)); \
        uint4 q3 = *reinterpret_cast<const uint4*>(vb + (R3)); \
        const uint32_t* qq[4] = {&q0.x, &q1.x, &q2.x, &q3.x}; \
        const float ww[4] = {V0, V1, V2, V3}; \
        _Pragma("unroll") \
        for (int cor = 0; cor < 4; cor++) { \
            uint64_t wt2 = packf2(ww[cor], ww[cor]); \
            _Pragma("unroll") \
            for (int u = 0; u < 4; u++) \
                ffma2(acc[u], wt2, h2_to_f2(qq[cor][u])); \
        } \
    } while (0)

    #pragma unroll
    for (int k = 0; k < 8; k++) {
        const int src = (g << 3) + k;
        float w0 = __shfl_sync(0xffffffffu, Wm[0], src);
        float w1 = __shfl_sync(0xffffffffu, Wm[1], src);
        float w2 = __shfl_sync(0xffffffffu, Wm[2], src);
        float w3 = __shfl_sync(0xffffffffu, Wm[3], src);
        int   r0 = __shfl_sync(0xffffffffu, Rm[0], src);
        int   r1 = __shfl_sync(0xffffffffu, Rm[1], src);
        int   r2 = __shfl_sync(0xffffffffu, Rm[2], src);
        int   r3 = __shfl_sync(0xffffffffu, Rm[3], src);
        ACC8(r0, r1, r2, r3, w0, w1, w2, w3);
    }
    ACC8(R8[0], R8[1], R8[2], R8[3], W8[0], W8[1], W8[2], W8[3]);
    #undef ACC8

    uint4 out;
    uint32_t* outw = &out.x;
    #pragma unroll
    for (int u = 0; u < 4; u++) {
        float ax, ay;
        unpackf2(acc[u], ax, ay);
        outw[u] = pack2h(__float2half_rn(ax), __float2half_rn(ay));
    }
    *reinterpret_cast<uint4*>(&sh[(size_t)p * 256 + cb]) = out;
}

// ---------------------------------------------------------------------------
extern "C" void kernel_launch(void* const* d_in, const int* in_sizes, int n_in,
                              void* d_out, int out_size)
{
    const float* x        = (const float*)d_in[0];
    const float* conv_w   = (const float*)d_in[1];
    const float* bn1_g    = (const float*)d_in[2];
    const float* bn1_b    = (const float*)d_in[3];
    const float* bn1_m    = (const float*)d_in[4];
    const float* bn1_v    = (const float*)d_in[5];
    const float* value_w  = (const float*)d_in[6];
    const float* value_b  = (const float*)d_in[7];
    const float* offset_w = (const float*)d_in[8];
    const float* offset_b = (const float*)d_in[9];
    const float* out_w    = (const float*)d_in[10];
    const float* out_b    = (const float*)d_in[11];
    const float* bn2_g    = (const float*)d_in[12];
    const float* bn2_b    = (const float*)d_in[13];
    const float* bn2_m    = (const float*)d_in[14];
    const float* bn2_v    = (const float*)d_in[15];

    fp16 *xh, *yh, *sh, *vv, *whi;
    float *omp;
    cudaGetSymbolAddress((void**)&xh,  g_xh);
    cudaGetSymbolAddress((void**)&yh,  g_yh);
    cudaGetSymbolAddress((void**)&sh,  g_sh);
    cudaGetSymbolAddress((void**)&vv,  g_v);
    cudaGetSymbolAddress((void**)&whi, g_whi);
    cudaGetSymbolAddress((void**)&omp, g_om);

    const int smem = 3 * 32768;   // 96KB: 3 x (16KB A + 16KB B)
    cudaFuncSetAttribute(gemm_fp16<1>, cudaFuncAttributeMaxDynamicSharedMemorySize, smem);
    cudaFuncSetAttribute(gemm_fp16<2>, cudaFuncAttributeMaxDynamicSharedMemorySize, smem);
    cudaFuncSetAttribute(gemm_fp16<3>, cudaFuncAttributeMaxDynamicSharedMemorySize, smem);

    // merged prepass: x transpose+cvt (4096 blocks) + weight cvt (896 blocks)
    prep<<<4992, 256>>>(x, xh, conv_w, value_w, offset_w, out_w, whi);

    const int MT = MTOT / 128;   // 512 pixel tiles

    // 1) y = silu(bn1(x @ conv_w^T))           -> y fp16
    gemm_fp16<1><<<dim3(2, MT), 256, smem>>>(
        xh, whi, nullptr, nullptr,
        bn1_g, bn1_b, bn1_m, bn1_v, nullptr, nullptr, yh);
    // 2) fused: v (fp16) = y@value_w^T + b ; om (fp32) = y@offset_w^T + b
    gemm_fp16<3><<<dim3(3, MT), 256, smem>>>(
        yh, whi + 256*256, value_b, offset_b,
        nullptr, nullptr, nullptr, nullptr, nullptr, omp, vv);
    // 3) deformable sampling (fp16 v) -> s fp16
    dcn_sample<<<MTOT / 8, 256>>>(vv, omp, sh);
    // 4) out = silu(bn2(s @ out_w^T + out_b))  -> NCHW fp32
    gemm_fp16<2><<<dim3(2, MT), 256, smem>>>(
        sh, whi + 640*256, out_b, nullptr,
        bn2_g, bn2_b, bn2_m, bn2_v, (float*)d_out, nullptr, nullptr);
}